// round 8
// baseline (speedup 1.0000x reference)
#include <cuda_runtime.h>
#include <cuda_fp16.h>

// ---- problem constants ----
#define Bb   32      // batch
#define Ii   32      // input capsules
#define AIN  16      // input atoms
#define OD   10      // output classes
#define OA   16      // output atoms
#define HWp  144     // 12*12 spatial
#define Kk   160     // OD*OA
#define Sp   8       // positions per block
#define NCH  (HWp/Sp)   // 18 chunks
#define VPAD 34      // padded capsule-dim stride in half2 (8B-aligned rows, low conflicts)

// dynamic smem layout (bytes)
#define VSM_H2     (4 * Kk * VPAD)                 // 21760 half2 = 87040 B
#define XS_OFF     (VSM_H2 * 4)                    // 87040
#define EX_OFF     (XS_OFF + Ii * AIN * Sp * 4)    // +16384 = 103424
#define SMEM_BYTES (EX_OFF + 2 * OD * 16 * 16)     // +5120  = 108544

// ============================================================================
// Fused kernel: block = (b, 8-position chunk). 320 threads = 10 warps.
// Phase 1: votes -> smem fp16, packed as half2(pos_even, pos_odd),
//          layout vsm[(q*160 + t)*VPAD + i],  q = position pair 0..3.
// Phase 2: routing per pair, warp = class d, lane = (i16, grp), both
//          positions of the pair interleaved in registers.
// ============================================================================
__global__ void __launch_bounds__(320, 2)
fused_kernel(const float* __restrict__ x, const float* __restrict__ w,
             const float* __restrict__ bias, float* __restrict__ out)
{
    extern __shared__ char smem_raw[];
    __half2* vsm = (__half2*)smem_raw;                    // votes
    float*   xs  = (float*)(smem_raw + XS_OFF);           // x tile [i][ain][8]
    float4*  ex  = (float4*)(smem_raw + EX_OFF);          // softmax exchange [2][OD][16]

    const int b   = blockIdx.x / NCH;
    const int hw0 = (blockIdx.x % NCH) * Sp;
    const int tid = threadIdx.x;

    // ---- load x tile: x[b, i, ain, hw0..hw0+7] ----
    for (int idx = tid; idx < Ii * AIN * Sp; idx += 320) {
        const int i   = idx >> 7;          // /(AIN*Sp)
        const int rem = idx & 127;
        const int ain = rem >> 3;
        const int p   = rem & 7;
        xs[idx] = x[((size_t)(b * Ii + i) * AIN + ain) * HWp + hw0 + p];
    }
    __syncthreads();

    // ================= Phase 1: votes =================
    // thread: t = tid%160 (= d*16+a, the weight column), h = tid/160 -> pos 4h..4h+3
    {
        const int t = tid % Kk;
        const int h = tid / Kk;
        for (int i = 0; i < Ii; i++) {
            float a0 = 0.f, a1 = 0.f, a2 = 0.f, a3 = 0.f;
#pragma unroll
            for (int ain = 0; ain < AIN; ain++) {
                const float  wv = w[(i * AIN + ain) * Kk + t];   // coalesced, L1/L2 hot
                const float4 xv = *(const float4*)&xs[(i * AIN + ain) * Sp + 4 * h];
                a0 = fmaf(wv, xv.x, a0);
                a1 = fmaf(wv, xv.y, a1);
                a2 = fmaf(wv, xv.z, a2);
                a3 = fmaf(wv, xv.w, a3);
            }
            // pair q=2h holds (pos 4h, 4h+1); q=2h+1 holds (4h+2, 4h+3)
            vsm[((2 * h)     * Kk + t) * VPAD + i] = __floats2half2_rn(a0, a1);
            vsm[((2 * h + 1) * Kk + t) * VPAD + i] = __floats2half2_rn(a2, a3);
        }
    }
    __syncthreads();

    // ================= Phase 2: routing =================
    const int d    = tid >> 5;             // warp = class
    const int lane = tid & 31;
    const int i16  = lane & 15;            // capsule pair index (capsules 2*i16, 2*i16+1)
    const int grp  = lane >> 4;            // atom half
    const int atom = grp * 8 + ((lane >> 1) & 7);
    const float bv = bias[d * OA + atom];
    const unsigned FULL = 0xffffffffu;

    for (int q = 0; q < Sp / 2; q++) {
        // ---- votes for this pair: 2 capsules x 2 positions x 8 atoms ----
        float va0p0[8], va0p1[8], va1p0[8], va1p1[8];
#pragma unroll
        for (int k = 0; k < 8; k++) {
            const int row = (q * Kk + d * OA + grp * 8 + k) * VPAD + 2 * i16;
            const uint2 u = *(const uint2*)&vsm[row];    // LDS.64: capsule c0 + c1
            const float2 f0 = __half22float2(*(const __half2*)&u.x);
            const float2 f1 = __half22float2(*(const __half2*)&u.y);
            va0p0[k] = f0.x; va0p1[k] = f0.y;
            va1p0[k] = f1.x; va1p1[k] = f1.y;
        }

        float lA0 = 0.f, lB0 = 0.f, lA1 = 0.f, lB1 = 0.f;   // logits (cap, pos)
        float P0 = 0.f, P1 = 0.f, sc0 = 0.f, sc1 = 0.f;

#pragma unroll
        for (int r = 0; r < 3; r++) {
            // ---- softmax over d ----
            float rA0, rB0, rA1, rB1;
            if (r == 0) {
                rA0 = rB0 = rA1 = rB1 = 0.1f;
            } else {
                const float eA0 = __expf(lA0), eB0 = __expf(lB0);
                const float eA1 = __expf(lA1), eB1 = __expf(lB1);
                if (grp == 0)
                    ex[(r - 1) * OD * 16 + d * 16 + i16] = make_float4(eA0, eB0, eA1, eB1);
                __syncthreads();
                float sA0 = 0.f, sB0 = 0.f, sA1 = 0.f, sB1 = 0.f;
#pragma unroll
                for (int d2 = 0; d2 < OD; d2++) {
                    const float4 v = ex[(r - 1) * OD * 16 + d2 * 16 + i16];
                    sA0 += v.x; sB0 += v.y; sA1 += v.z; sB1 += v.w;
                }
                rA0 = __fdividef(eA0, sA0); rB0 = __fdividef(eB0, sB0);
                rA1 = __fdividef(eA1, sA1); rB1 = __fdividef(eB1, sB1);
            }

            // ---- weighted votes for own-group atoms, both positions ----
            float q0[8], q1[8];
#pragma unroll
            for (int k = 0; k < 8; k++) {
                q0[k] = fmaf(rB0, va1p0[k], rA0 * va0p0[k]);
                q1[k] = fmaf(rB1, va1p1[k], rA1 * va0p1[k]);
            }

            // ---- atom-splitting reduce over 16-lane half (both positions) ----
            {
                const bool hi = (lane & 8) != 0;
#pragma unroll
                for (int k = 0; k < 4; k++) {
                    float s0 = hi ? q0[k] : q0[k + 4];
                    float s1 = hi ? q1[k] : q1[k + 4];
                    float r0 = __shfl_xor_sync(FULL, s0, 8);
                    float r1 = __shfl_xor_sync(FULL, s1, 8);
                    q0[k] = (hi ? q0[k + 4] : q0[k]) + r0;
                    q1[k] = (hi ? q1[k + 4] : q1[k]) + r1;
                }
            }
            {
                const bool hi = (lane & 4) != 0;
#pragma unroll
                for (int k = 0; k < 2; k++) {
                    float s0 = hi ? q0[k] : q0[k + 2];
                    float s1 = hi ? q1[k] : q1[k + 2];
                    float r0 = __shfl_xor_sync(FULL, s0, 4);
                    float r1 = __shfl_xor_sync(FULL, s1, 4);
                    q0[k] = (hi ? q0[k + 2] : q0[k]) + r0;
                    q1[k] = (hi ? q1[k + 2] : q1[k]) + r1;
                }
            }
            float s0v, s1v;
            {
                const bool hi = (lane & 2) != 0;
                float s0 = hi ? q0[0] : q0[1];
                float s1 = hi ? q1[0] : q1[1];
                float r0 = __shfl_xor_sync(FULL, s0, 2);
                float r1 = __shfl_xor_sync(FULL, s1, 2);
                s0v = (hi ? q0[1] : q0[0]) + r0;
                s1v = (hi ? q1[1] : q1[0]) + r1;
            }
            s0v += __shfl_xor_sync(FULL, s0v, 1);
            s1v += __shfl_xor_sync(FULL, s1v, 1);

            P0 = s0v + bv;                  // pre-squash preact for `atom`, pos even
            P1 = s1v + bv;                  // pos odd

            if (r < 2) {
                // ---- broadcast own-group pre-squash atoms ----
                float act0[8], act1[8];
#pragma unroll
                for (int k = 0; k < 8; k++) {
                    const int src = (lane & 16) | (k << 1);
                    act0[k] = __shfl_sync(FULL, P0, src);
                    act1[k] = __shfl_sync(FULL, P1, src);
                }
                float n0 = 0.f, n1 = 0.f;
#pragma unroll
                for (int k = 0; k < 8; k++) {
                    n0 = fmaf(act0[k], act0[k], n0);
                    n1 = fmaf(act1[k], act1[k], n1);
                }
                n0 += __shfl_xor_sync(FULL, n0, 16);
                n1 += __shfl_xor_sync(FULL, n1, 16);
                const float g0 = __fdividef(sqrtf(n0), 1.f + n0);
                const float g1 = __fdividef(sqrtf(n1), 1.f + n1);

                float dA0 = 0.f, dB0 = 0.f, dA1 = 0.f, dB1 = 0.f;
#pragma unroll
                for (int k = 0; k < 8; k++) {
                    dA0 = fmaf(va0p0[k], act0[k], dA0);
                    dB0 = fmaf(va1p0[k], act0[k], dB0);
                    dA1 = fmaf(va0p1[k], act1[k], dA1);
                    dB1 = fmaf(va1p1[k], act1[k], dB1);
                }
                dA0 += __shfl_xor_sync(FULL, dA0, 16);
                dB0 += __shfl_xor_sync(FULL, dB0, 16);
                dA1 += __shfl_xor_sync(FULL, dA1, 16);
                dB1 += __shfl_xor_sync(FULL, dB1, 16);
                lA0 = fmaf(dA0, g0, lA0);  lB0 = fmaf(dB0, g0, lB0);
                lA1 = fmaf(dA1, g1, lA1);  lB1 = fmaf(dB1, g1, lB1);
            } else {
                // ---- final squash norms via square-butterfly ----
                float sq0 = P0 * P0, sq1 = P1 * P1;
#pragma unroll
                for (int off = 16; off; off >>= 1) {
                    sq0 += __shfl_xor_sync(FULL, sq0, off);
                    sq1 += __shfl_xor_sync(FULL, sq1, off);
                }
                const float n0 = 0.5f * sq0;   // each atom counted twice
                const float n1 = 0.5f * sq1;
                sc0 = __fdividef(sqrtf(n0), 1.f + n0);
                sc1 = __fdividef(sqrtf(n1), 1.f + n1);
            }
        }

        // ---- output: even lane writes pos 2q, odd lane writes pos 2q+1 ----
        const float val = (lane & 1) ? P1 * sc1 : P0 * sc0;
        out[((size_t)(b * OD + d) * OA + atom) * HWp + hw0 + 2 * q + (lane & 1)] = val;
    }
}

extern "C" void kernel_launch(void* const* d_in, const int* in_sizes, int n_in,
                              void* d_out, int out_size)
{
    const float* x    = (const float*)d_in[0];   // [32,32,16,12,12]
    const float* w    = (const float*)d_in[1];   // [32,16,160]
    const float* bias = (const float*)d_in[2];   // [10,16,1,1]
    float* out = (float*)d_out;                  // [32,10,16,12,12]

    cudaFuncSetAttribute(fused_kernel,
                         cudaFuncAttributeMaxDynamicSharedMemorySize, SMEM_BYTES);
    fused_kernel<<<Bb * NCH, 320, SMEM_BYTES>>>(x, w, bias, out);
}